// round 1
// baseline (speedup 1.0000x reference)
#include <cuda_runtime.h>
#include <cuda_bf16.h>

#define H 40
#define T 256
#define BATCH 8192
#define EPB 32            // elements per block
#define TPE 8             // threads per element
#define KOWN 5            // hidden units owned per thread
#define THREADS (EPB * TPE)
#define NBLOCKS (BATCH / EPB)

// shared memory layout (in floats)
#define OFF_WIH1 0                      // [40][3][4]   = 480
#define OFF_WHH1 480                    // [40][41][4]  = 6560 (pitch-padded float4 rows)
#define OFF_WIH2 (480 + 6560)           // 7040
#define OFF_WHH2 (7040 + 6560)          // 13600
#define OFF_H1   (13600 + 6560)         // 20160 : [2][32][41]
#define OFF_H2   (20160 + 2624)         // 22784 : [2][32][41]
#define SMEM_FLOATS (22784 + 2624)      // 25408
#define SMEM_BYTES (SMEM_FLOATS * 4)    // 101632

__device__ __forceinline__ float sigf(float x) {
    return __fdividef(1.0f, 1.0f + __expf(-x));
}
__device__ __forceinline__ float tanh_(float x) {
    float e = __expf(-2.0f * x);
    return __fdividef(1.0f - e, 1.0f + e);
}

__global__ __launch_bounds__(THREADS, 2)
void lstm2_fused_kernel(const float* __restrict__ x,
                        const float* __restrict__ W_ih1,
                        const float* __restrict__ W_hh1,
                        const float* __restrict__ b1,
                        const float* __restrict__ W_ih2,
                        const float* __restrict__ W_hh2,
                        const float* __restrict__ b2,
                        const float* __restrict__ W_fc,
                        const float* __restrict__ b_fc,
                        float* __restrict__ out)
{
    extern __shared__ float sm[];
    const int tid  = threadIdx.x;

    // ---- stage weights into smem, gate-interleaved ----
    // W_ih1 [160][3] -> sm[(k*3+c)*4 + g]
    for (int idx = tid; idx < 160 * 3; idx += THREADS) {
        int row = idx / 3, c = idx % 3;
        int g = row / H, k = row % H;
        sm[OFF_WIH1 + (k * 3 + c) * 4 + g] = W_ih1[idx];
    }
    // W_hh1 [160][40] -> sm[(k*41+kk)*4 + g]
    for (int idx = tid; idx < 160 * H; idx += THREADS) {
        int row = idx / H, kk = idx % H;
        int g = row / H, k = row % H;
        sm[OFF_WHH1 + (k * 41 + kk) * 4 + g] = W_hh1[idx];
    }
    for (int idx = tid; idx < 160 * H; idx += THREADS) {
        int row = idx / H, kk = idx % H;
        int g = row / H, k = row % H;
        sm[OFF_WIH2 + (k * 41 + kk) * 4 + g] = W_ih2[idx];
    }
    for (int idx = tid; idx < 160 * H; idx += THREADS) {
        int row = idx / H, kk = idx % H;
        int g = row / H, k = row % H;
        sm[OFF_WHH2 + (k * 41 + kk) * 4 + g] = W_hh2[idx];
    }
    // zero h buffers
    for (int idx = tid; idx < 2 * EPB * 41; idx += THREADS) {
        sm[OFF_H1 + idx] = 0.0f;
        sm[OFF_H2 + idx] = 0.0f;
    }
    __syncthreads();

    const int lane = tid & 31;
    const int warp = tid >> 5;
    const int ew   = lane >> 3;        // element within warp (0..3)
    const int j    = lane & 7;         // k-slice within element (0..7)
    const int e    = warp * 4 + ew;    // element within block (0..31)
    const int k0   = j * KOWN;
    const long gelem = (long)blockIdx.x * EPB + e;

    const float4* __restrict__ Wih1v = (const float4*)(sm + OFF_WIH1);
    const float4* __restrict__ Whh1v = (const float4*)(sm + OFF_WHH1);
    const float4* __restrict__ Wih2v = (const float4*)(sm + OFF_WIH2);
    const float4* __restrict__ Whh2v = (const float4*)(sm + OFF_WHH2);
    float* __restrict__ H1 = sm + OFF_H1;
    float* __restrict__ H2 = sm + OFF_H2;

    // biases into registers (gate-interleaved per owned k)
    float b1r[KOWN][4], b2r[KOWN][4];
    #pragma unroll
    for (int k = 0; k < KOWN; k++)
        #pragma unroll
        for (int g = 0; g < 4; g++) {
            b1r[k][g] = b1[g * H + k0 + k];
            b2r[k][g] = b2[g * H + k0 + k];
        }

    float c1[KOWN], c2[KOWN];
    #pragma unroll
    for (int k = 0; k < KOWN; k++) { c1[k] = 0.0f; c2[k] = 0.0f; }

    const float* xptr = x + gelem * (T * 3);
    float x0 = xptr[0], x1 = xptr[1], x2 = xptr[2];

    int p = 0;
    for (int t = 0; t < T; t++) {
        // ================= layer 1 =================
        float a0[KOWN], a1[KOWN], a2[KOWN], a3[KOWN];
        #pragma unroll
        for (int k = 0; k < KOWN; k++) {
            a0[k] = b1r[k][0]; a1[k] = b1r[k][1];
            a2[k] = b1r[k][2]; a3[k] = b1r[k][3];
        }
        // input contribution (3-dim x)
        #pragma unroll
        for (int k = 0; k < KOWN; k++) {
            float4 w0 = Wih1v[(k0 + k) * 3 + 0];
            float4 w1 = Wih1v[(k0 + k) * 3 + 1];
            float4 w2 = Wih1v[(k0 + k) * 3 + 2];
            a0[k] = fmaf(x0, w0.x, a0[k]); a0[k] = fmaf(x1, w1.x, a0[k]); a0[k] = fmaf(x2, w2.x, a0[k]);
            a1[k] = fmaf(x0, w0.y, a1[k]); a1[k] = fmaf(x1, w1.y, a1[k]); a1[k] = fmaf(x2, w2.y, a1[k]);
            a2[k] = fmaf(x0, w0.z, a2[k]); a2[k] = fmaf(x1, w1.z, a2[k]); a2[k] = fmaf(x2, w2.z, a2[k]);
            a3[k] = fmaf(x0, w0.w, a3[k]); a3[k] = fmaf(x1, w1.w, a3[k]); a3[k] = fmaf(x2, w2.w, a3[k]);
        }
        // recurrent contribution
        {
            const float* h1p = H1 + (p * EPB + e) * 41;
            #pragma unroll 8
            for (int kk = 0; kk < H; kk++) {
                float hv = h1p[kk];
                #pragma unroll
                for (int k = 0; k < KOWN; k++) {
                    float4 w = Whh1v[(k0 + k) * 41 + kk];
                    a0[k] = fmaf(hv, w.x, a0[k]);
                    a1[k] = fmaf(hv, w.y, a1[k]);
                    a2[k] = fmaf(hv, w.z, a2[k]);
                    a3[k] = fmaf(hv, w.w, a3[k]);
                }
            }
        }
        float* h1n = H1 + ((1 - p) * EPB + e) * 41;
        #pragma unroll
        for (int k = 0; k < KOWN; k++) {
            float ig = sigf(a0[k]);
            float fg = sigf(a1[k]);
            float gg = tanh_(a2[k]);
            float og = sigf(a3[k]);
            c1[k] = fmaf(fg, c1[k], ig * gg);
            h1n[k0 + k] = og * tanh_(c1[k]);
        }
        __syncwarp();

        // prefetch next x while layer-2 math runs
        float nx0 = x0, nx1 = x1, nx2 = x2;
        if (t < T - 1) {
            const float* xn = xptr + (t + 1) * 3;
            nx0 = xn[0]; nx1 = xn[1]; nx2 = xn[2];
        }

        // ================= layer 2 =================
        #pragma unroll
        for (int k = 0; k < KOWN; k++) {
            a0[k] = b2r[k][0]; a1[k] = b2r[k][1];
            a2[k] = b2r[k][2]; a3[k] = b2r[k][3];
        }
        {
            const float* h1c = h1n;  // layer-1 output at this timestep
            #pragma unroll 8
            for (int kk = 0; kk < H; kk++) {
                float hv = h1c[kk];
                #pragma unroll
                for (int k = 0; k < KOWN; k++) {
                    float4 w = Wih2v[(k0 + k) * 41 + kk];
                    a0[k] = fmaf(hv, w.x, a0[k]);
                    a1[k] = fmaf(hv, w.y, a1[k]);
                    a2[k] = fmaf(hv, w.z, a2[k]);
                    a3[k] = fmaf(hv, w.w, a3[k]);
                }
            }
            const float* h2p = H2 + (p * EPB + e) * 41;
            #pragma unroll 8
            for (int kk = 0; kk < H; kk++) {
                float hv = h2p[kk];
                #pragma unroll
                for (int k = 0; k < KOWN; k++) {
                    float4 w = Whh2v[(k0 + k) * 41 + kk];
                    a0[k] = fmaf(hv, w.x, a0[k]);
                    a1[k] = fmaf(hv, w.y, a1[k]);
                    a2[k] = fmaf(hv, w.z, a2[k]);
                    a3[k] = fmaf(hv, w.w, a3[k]);
                }
            }
        }
        float* h2n = H2 + ((1 - p) * EPB + e) * 41;
        #pragma unroll
        for (int k = 0; k < KOWN; k++) {
            float ig = sigf(a0[k]);
            float fg = sigf(a1[k]);
            float gg = tanh_(a2[k]);
            float og = sigf(a3[k]);
            c2[k] = fmaf(fg, c2[k], ig * gg);
            h2n[k0 + k] = og * tanh_(c2[k]);
        }
        __syncwarp();

        x0 = nx0; x1 = nx1; x2 = nx2;
        p ^= 1;
    }

    // ================= FC epilogue =================
    // after the loop, h_{T-1} of layer 2 lives in buffer index p
    if (j < 2) {
        const float* h2f = H2 + (p * EPB + e) * 41;
        float acc = b_fc[j];
        #pragma unroll 8
        for (int kk = 0; kk < H; kk++)
            acc = fmaf(h2f[kk], W_fc[j * H + kk], acc);
        out[gelem * 2 + j] = acc;
    }
}

extern "C" void kernel_launch(void* const* d_in, const int* in_sizes, int n_in,
                              void* d_out, int out_size)
{
    const float* x     = (const float*)d_in[0];
    const float* W_ih1 = (const float*)d_in[1];
    const float* W_hh1 = (const float*)d_in[2];
    const float* b1    = (const float*)d_in[3];
    const float* W_ih2 = (const float*)d_in[4];
    const float* W_hh2 = (const float*)d_in[5];
    const float* b2    = (const float*)d_in[6];
    const float* W_fc  = (const float*)d_in[7];
    const float* b_fc  = (const float*)d_in[8];
    float* out = (float*)d_out;

    cudaFuncSetAttribute(lstm2_fused_kernel,
                         cudaFuncAttributeMaxDynamicSharedMemorySize, SMEM_BYTES);

    lstm2_fused_kernel<<<NBLOCKS, THREADS, SMEM_BYTES>>>(
        x, W_ih1, W_hh1, b1, W_ih2, W_hh2, b2, W_fc, b_fc, out);
}

// round 2
// speedup vs baseline: 1.8787x; 1.8787x over previous
#include <cuda_runtime.h>
#include <cuda_bf16.h>

#define H 40
#define T 256
#define BATCH 8192
#define EPB 32            // elements per block
#define THREADS 64        // 2 warps, 16 elements per warp, 4 per thread
#define NBLOCKS (BATCH / EPB)   // 256

typedef unsigned long long u64;

// ---- shared memory layout (float offsets) ----
#define OFF_WIH1 0                       // [k 40][c 3][g 4]      = 480
#define OFF_B1   480                     // [k 40][g 4]           = 160
#define OFF_B2   640                     // [k 40][g 4]           = 160
#define OFF_WHH1 800                     // [k 40][kk pitch41][g4]= 6560
#define OFF_WIH2 (800 + 6560)            // 7360
#define OFF_WHH2 (800 + 2*6560)         // 13920
#define OFF_H1   (800 + 3*6560)         // 20480 : [e 32][kk pitch41] x float2{h,h} = 2624 floats
#define OFF_H2   (OFF_H1 + 2624)         // 23104
#define SMEM_FLOATS (OFF_H2 + 2624)      // 25728
#define SMEM_BYTES (SMEM_FLOATS * 4)     // 102912

__device__ __forceinline__ void fma2(u64 &d, u64 a, u64 b) {
    asm("fma.rn.f32x2 %0, %1, %2, %0;" : "+l"(d) : "l"(a), "l"(b));
}
__device__ __forceinline__ u64 pack2(float x, float y) {
    u64 r; asm("mov.b64 %0, {%1, %2};" : "=l"(r) : "f"(x), "f"(y)); return r;
}
__device__ __forceinline__ void unpack2(u64 v, float &x, float &y) {
    asm("mov.b64 {%0, %1}, %2;" : "=f"(x), "=f"(y) : "l"(v));
}
__device__ __forceinline__ float sigf(float x) {
    return __fdividef(1.0f, 1.0f + __expf(-x));
}
__device__ __forceinline__ float tanh_(float x) {
    float e = __expf(-2.0f * x);
    return __fdividef(1.0f - e, 1.0f + e);
}

__global__ __launch_bounds__(THREADS)
void lstm2_fused_kernel(const float* __restrict__ x,
                        const float* __restrict__ W_ih1,
                        const float* __restrict__ W_hh1,
                        const float* __restrict__ b1,
                        const float* __restrict__ W_ih2,
                        const float* __restrict__ W_hh2,
                        const float* __restrict__ b2,
                        const float* __restrict__ W_fc,
                        const float* __restrict__ b_fc,
                        float* __restrict__ out)
{
    extern __shared__ float sm[];
    const int tid = threadIdx.x;

    // ---- stage weights, gate-interleaved ----
    for (int idx = tid; idx < 160 * 3; idx += THREADS) {
        int row = idx / 3, c = idx % 3;
        int g = row / H, k = row % H;
        sm[OFF_WIH1 + (k * 3 + c) * 4 + g] = W_ih1[idx];
    }
    for (int idx = tid; idx < 160; idx += THREADS) {
        int g = idx / H, k = idx % H;
        sm[OFF_B1 + k * 4 + g] = b1[idx];
        sm[OFF_B2 + k * 4 + g] = b2[idx];
    }
    for (int idx = tid; idx < 160 * H; idx += THREADS) {
        int row = idx / H, kk = idx % H;
        int g = row / H, k = row % H;
        sm[OFF_WHH1 + (k * 41 + kk) * 4 + g] = W_hh1[idx];
        sm[OFF_WIH2 + (k * 41 + kk) * 4 + g] = W_ih2[idx];
        sm[OFF_WHH2 + (k * 41 + kk) * 4 + g] = W_hh2[idx];
    }
    for (int idx = tid; idx < 2 * 2624; idx += THREADS) {
        sm[OFF_H1 + idx] = 0.0f;   // covers H1 and H2 (contiguous)
    }
    __syncthreads();

    const int lane = tid & 31;
    const int warp = tid >> 5;
    const int j    = lane & 7;     // k-slice (owns k0..k0+4)
    const int sub  = lane >> 3;    // element subgroup within warp
    const int k0   = j * 5;

    int eb[4];                     // element index within block
    long ge[4];                    // global element index
    const float* xb[4];
    #pragma unroll
    for (int b = 0; b < 4; b++) {
        eb[b] = warp * 16 + sub * 4 + b;
        ge[b] = (long)blockIdx.x * EPB + eb[b];
        xb[b] = x + ge[b] * (T * 3);
    }

    float c1[5][4], c2[5][4];
    #pragma unroll
    for (int k = 0; k < 5; k++)
        #pragma unroll
        for (int b = 0; b < 4; b++) { c1[k][b] = 0.0f; c2[k][b] = 0.0f; }

    // x for t=0
    float xv[4][3];
    #pragma unroll
    for (int b = 0; b < 4; b++)
        #pragma unroll
        for (int c = 0; c < 3; c++)
            xv[b][c] = __ldg(xb[b] + c);

    for (int t = 0; t < T; t++) {
        // prefetch next x early
        float xn[4][3];
        {
            int tn = (t + 1 < T) ? (t + 1) : (T - 1);
            #pragma unroll
            for (int b = 0; b < 4; b++)
                #pragma unroll
                for (int c = 0; c < 3; c++)
                    xn[b][c] = __ldg(xb[b] + tn * 3 + c);
        }

        // ================= layer 1 =================
        u64 aA[5][4], aB[5][4];   // aA = (i,f) packed, aB = (g,o) packed
        #pragma unroll
        for (int k = 0; k < 5; k++) {
            ulonglong2 bb = *(const ulonglong2*)(sm + OFF_B1 + (k0 + k) * 4);
            #pragma unroll
            for (int b = 0; b < 4; b++) { aA[k][b] = bb.x; aB[k][b] = bb.y; }
        }
        // input contribution
        #pragma unroll
        for (int c = 0; c < 3; c++) {
            u64 xp[4];
            #pragma unroll
            for (int b = 0; b < 4; b++) xp[b] = pack2(xv[b][c], xv[b][c]);
            #pragma unroll
            for (int k = 0; k < 5; k++) {
                ulonglong2 w = *(const ulonglong2*)(sm + OFF_WIH1 + ((k0 + k) * 3 + c) * 4);
                #pragma unroll
                for (int b = 0; b < 4; b++) {
                    fma2(aA[k][b], w.x, xp[b]);
                    fma2(aB[k][b], w.y, xp[b]);
                }
            }
        }
        // recurrent contribution
        #pragma unroll 2
        for (int kk = 0; kk < H; kk++) {
            u64 hp[4];
            #pragma unroll
            for (int b = 0; b < 4; b++)
                hp[b] = *(const u64*)(sm + OFF_H1 + (eb[b] * 41 + kk) * 2);
            #pragma unroll
            for (int k = 0; k < 5; k++) {
                ulonglong2 w = *(const ulonglong2*)(sm + OFF_WHH1 + ((k0 + k) * 41 + kk) * 4);
                #pragma unroll
                for (int b = 0; b < 4; b++) {
                    fma2(aA[k][b], w.x, hp[b]);
                    fma2(aB[k][b], w.y, hp[b]);
                }
            }
        }
        __syncwarp();   // all reads of old H1 done
        #pragma unroll
        for (int k = 0; k < 5; k++) {
            #pragma unroll
            for (int b = 0; b < 4; b++) {
                float gi, gf, gg, go;
                unpack2(aA[k][b], gi, gf);
                unpack2(aB[k][b], gg, go);
                gi = sigf(gi); gf = sigf(gf); gg = tanh_(gg); go = sigf(go);
                c1[k][b] = fmaf(gf, c1[k][b], gi * gg);
                float h = go * tanh_(c1[k][b]);
                *(u64*)(sm + OFF_H1 + (eb[b] * 41 + k0 + k) * 2) = pack2(h, h);
            }
        }
        __syncwarp();   // H1 new visible

        // ================= layer 2 (ih2 + hh2 fused) =================
        #pragma unroll
        for (int k = 0; k < 5; k++) {
            ulonglong2 bb = *(const ulonglong2*)(sm + OFF_B2 + (k0 + k) * 4);
            #pragma unroll
            for (int b = 0; b < 4; b++) { aA[k][b] = bb.x; aB[k][b] = bb.y; }
        }
        #pragma unroll 2
        for (int kk = 0; kk < H; kk++) {
            u64 h1p[4], h2p[4];
            #pragma unroll
            for (int b = 0; b < 4; b++) {
                h1p[b] = *(const u64*)(sm + OFF_H1 + (eb[b] * 41 + kk) * 2);
                h2p[b] = *(const u64*)(sm + OFF_H2 + (eb[b] * 41 + kk) * 2);
            }
            #pragma unroll
            for (int k = 0; k < 5; k++) {
                ulonglong2 w1 = *(const ulonglong2*)(sm + OFF_WIH2 + ((k0 + k) * 41 + kk) * 4);
                ulonglong2 w2 = *(const ulonglong2*)(sm + OFF_WHH2 + ((k0 + k) * 41 + kk) * 4);
                #pragma unroll
                for (int b = 0; b < 4; b++) {
                    fma2(aA[k][b], w1.x, h1p[b]);
                    fma2(aB[k][b], w1.y, h1p[b]);
                    fma2(aA[k][b], w2.x, h2p[b]);
                    fma2(aB[k][b], w2.y, h2p[b]);
                }
            }
        }
        __syncwarp();   // all reads of old H2 done
        #pragma unroll
        for (int k = 0; k < 5; k++) {
            #pragma unroll
            for (int b = 0; b < 4; b++) {
                float gi, gf, gg, go;
                unpack2(aA[k][b], gi, gf);
                unpack2(aB[k][b], gg, go);
                gi = sigf(gi); gf = sigf(gf); gg = tanh_(gg); go = sigf(go);
                c2[k][b] = fmaf(gf, c2[k][b], gi * gg);
                float h = go * tanh_(c2[k][b]);
                *(u64*)(sm + OFF_H2 + (eb[b] * 41 + k0 + k) * 2) = pack2(h, h);
            }
        }
        __syncwarp();   // H2 new visible

        #pragma unroll
        for (int b = 0; b < 4; b++) {
            xv[b][0] = xn[b][0]; xv[b][1] = xn[b][1]; xv[b][2] = xn[b][2];
        }
    }

    // ================= FC epilogue =================
    if (j < 2) {
        float wfc[H];
        #pragma unroll 8
        for (int kk = 0; kk < H; kk++) wfc[kk] = W_fc[j * H + kk];
        float bias = b_fc[j];
        #pragma unroll
        for (int b = 0; b < 4; b++) {
            float acc = bias;
            #pragma unroll 8
            for (int kk = 0; kk < H; kk++) {
                float hlo, hhi;
                unpack2(*(const u64*)(sm + OFF_H2 + (eb[b] * 41 + kk) * 2), hlo, hhi);
                acc = fmaf(hlo, wfc[kk], acc);
            }
            out[ge[b] * 2 + j] = acc;
        }
    }
}

extern "C" void kernel_launch(void* const* d_in, const int* in_sizes, int n_in,
                              void* d_out, int out_size)
{
    const float* x     = (const float*)d_in[0];
    const float* W_ih1 = (const float*)d_in[1];
    const float* W_hh1 = (const float*)d_in[2];
    const float* b1    = (const float*)d_in[3];
    const float* W_ih2 = (const float*)d_in[4];
    const float* W_hh2 = (const float*)d_in[5];
    const float* b2    = (const float*)d_in[6];
    const float* W_fc  = (const float*)d_in[7];
    const float* b_fc  = (const float*)d_in[8];
    float* out = (float*)d_out;

    cudaFuncSetAttribute(lstm2_fused_kernel,
                         cudaFuncAttributeMaxDynamicSharedMemorySize, SMEM_BYTES);

    lstm2_fused_kernel<<<NBLOCKS, THREADS, SMEM_BYTES>>>(
        x, W_ih1, W_hh1, b1, W_ih2, W_hh2, b2, W_fc, b_fc, out);
}